// round 11
// baseline (speedup 1.0000x reference)
#include <cuda_runtime.h>
#include <cstdint>

#define DB 2     // batch
#define DL 64    // L
#define DT 32    // T
#define DD 256   // D
#define G  8     // j-columns per tile
#define NTILES (DB * DL * DL / G)   // 1024
#define ITEM_BYTES (DT * DD * 4)    // 32768 per tensor per item

// Scratch (device globals: no allocation allowed)
__device__ float g_Qk[DB * DL * DD];      // per (b,i): ((q@Wq^T+bq)/16)@Wk
__device__ float g_WcombP[64 * DD * 4];   // packed: [d4][f][4] = Wcomb[4*d4+r][f]
__device__ float g_bcomb[DD];             // bcomb[f] = sum_e Wf[f,e]*bv[e] + bf[f]
__device__ int   g_ticket;                // dynamic tile ticket

// ---------------------------------------------------------------------------
// f32x2 packed-FMA + cp.async helpers
// ---------------------------------------------------------------------------
__device__ __forceinline__ unsigned long long ffma2(unsigned long long a,
                                                    unsigned long long b,
                                                    unsigned long long c) {
    unsigned long long d;
    asm("fma.rn.f32x2 %0, %1, %2, %3;" : "=l"(d) : "l"(a), "l"(b), "l"(c));
    return d;
}
__device__ __forceinline__ unsigned long long mul2(unsigned long long a,
                                                   unsigned long long b) {
    unsigned long long d;
    asm("mul.rn.f32x2 %0, %1, %2;" : "=l"(d) : "l"(a), "l"(b));
    return d;
}
__device__ __forceinline__ unsigned long long f2_pack(float lo, float hi) {
    unsigned long long r;
    asm("mov.b64 %0, {%1, %2};" : "=l"(r) : "f"(lo), "f"(hi));
    return r;
}
__device__ __forceinline__ float f2_hsum(unsigned long long v) {
    float lo, hi;
    asm("mov.b64 {%0, %1}, %2;" : "=f"(lo), "=f"(hi) : "l"(v));
    return lo + hi;
}
__device__ __forceinline__ void cp16(uint32_t d, const void* s) {
    asm volatile("cp.async.cg.shared.global [%0], [%1], 16;"
                 :: "r"(d), "l"(s) : "memory");
}
__device__ __forceinline__ void cpcommit() {
    asm volatile("cp.async.commit_group;" ::: "memory");
}
__device__ __forceinline__ void cpwait1() {
    asm volatile("cp.async.wait_group 1;" ::: "memory");
}
__device__ __forceinline__ void cpwait0() {
    asm volatile("cp.async.wait_group 0;" ::: "memory");
}
__device__ __forceinline__ float fold2(float x, float y, int o, int lane) {
    const bool hi = (lane & o) != 0;
    const float send = hi ? x : y;
    const float recv = __shfl_xor_sync(0xffffffffu, send, o);
    return (hi ? y : x) + recv;
}

// ---------------------------------------------------------------------------
// Single prologue kernel, block = (32,32) = 1024 threads. (round-9, unchanged)
// ---------------------------------------------------------------------------
__global__ void prologue_kernel(const float* __restrict__ query,
                                const float* __restrict__ Wq,
                                const float* __restrict__ bq,
                                const float* __restrict__ Wk,
                                const float* __restrict__ Wv,
                                const float* __restrict__ bv,
                                const float* __restrict__ Wf,
                                const float* __restrict__ bf) {
    const int tx = threadIdx.x, ty = threadIdx.y;
    const int tid = ty * 32 + tx;
    const int blk = blockIdx.x;

    if (blk < 64) {
        __shared__ float Av[2][32][33];
        __shared__ float Bf[2][32][33];
        const int f0 = (blk & 7) * 32;
        const int d0 = (blk >> 3) * 32;

        Av[0][ty][tx] = Wv[(size_t)ty * DD + d0 + tx];
        Bf[0][ty][tx] = Wf[(size_t)(f0 + ty) * DD + tx];
        __syncthreads();

        float acc = 0.f;
#pragma unroll
        for (int s = 0; s < 8; s++) {
            const int cur = s & 1;
            if (s < 7) {
                const int e0 = (s + 1) * 32;
                Av[cur ^ 1][ty][tx] = Wv[(size_t)(e0 + ty) * DD + d0 + tx];
                Bf[cur ^ 1][ty][tx] = Wf[(size_t)(f0 + ty) * DD + e0 + tx];
            }
#pragma unroll
            for (int k = 0; k < 32; k++) acc += Av[cur][k][ty] * Bf[cur][tx][k];
            __syncthreads();
        }
        const int d = d0 + ty;
        const int f = f0 + tx;
        g_WcombP[(size_t)(d >> 2) * (DD * 4) + f * 4 + (d & 3)] = acc;

    } else if (blk < 192) {
        const int bi = blk - 64;
        __shared__ float q[DD];
        __shared__ float Qs[DD];
        __shared__ float part[4][DD];

        if (tid < DD) q[tid] = query[bi * DD + tid];
        __syncthreads();

#pragma unroll
        for (int i = 0; i < 8; i++) {
            const int e = ty * 8 + i;
            const float* wq = Wq + (size_t)e * DD;
            float p = 0.f;
#pragma unroll
            for (int c = 0; c < 8; c++) p += q[tx + 32 * c] * wq[tx + 32 * c];
#pragma unroll
            for (int off = 16; off; off >>= 1)
                p += __shfl_xor_sync(0xffffffffu, p, off);
            if (tx == 0) Qs[e] = (p + bq[e]) * 0.0625f;
        }
        __syncthreads();

        const int quarter = ty >> 3;
        const int d = tx + (ty & 7) * 32;
        const int e0 = quarter * 64;
        float acc = 0.f;
#pragma unroll 8
        for (int e = 0; e < 64; e++)
            acc += Qs[e0 + e] * Wk[(size_t)(e0 + e) * DD + d];
        part[quarter][d] = acc;
        __syncthreads();
        if (tid < DD)
            g_Qk[bi * DD + tid] = part[0][tid] + part[1][tid] + part[2][tid] + part[3][tid];

    } else {
        if (tid == 0) g_ticket = 0;
        __shared__ float bvs[DD];
        if (tid < DD) bvs[tid] = bv[tid];
        __syncthreads();
#pragma unroll
        for (int i = 0; i < 8; i++) {
            const int f = ty * 8 + i;
            const float* wf = Wf + (size_t)f * DD;
            float p = 0.f;
#pragma unroll
            for (int c = 0; c < 8; c++) p += bvs[tx + 32 * c] * wf[tx + 32 * c];
#pragma unroll
            for (int off = 16; off; off >>= 1)
                p += __shfl_xor_sync(0xffffffffu, p, off);
            if (tx == 0) g_bcomb[f] = p + bf[f];
        }
    }
}

// ---------------------------------------------------------------------------
// Chunk = rows (tA, tA+16) of one tensor, 2KB, staged into a per-warp slot.
// Each lane copies (and later reads) exactly its own 4x16B -> no syncwarp.
// ---------------------------------------------------------------------------
__device__ __forceinline__ void issue_chunk(uint32_t slot, const char* item,
                                            int tA, int lane) {
    const char* rA = item + tA * (DD * 4);
    const char* rB = item + (tA + 16) * (DD * 4);
    const uint32_t o = lane * 16;
    cp16(slot + o,        rA + o);
    cp16(slot + 512 + o,  rA + 512 + o);
    cp16(slot + 1024 + o, rB + o);
    cp16(slot + 1536 + o, rB + 512 + o);
    cpcommit();
}

__device__ __forceinline__ float score_chunk(const float* slot, int lane,
                                             const ulonglong2 q0,
                                             const ulonglong2 q1) {
    const ulonglong2* s2 = reinterpret_cast<const ulonglong2*>(slot);
    const ulonglong2 a0 = s2[lane],      a1 = s2[32 + lane];
    const ulonglong2 b0 = s2[64 + lane], b1 = s2[96 + lane];
    const float sa = f2_hsum(ffma2(a0.x, q0.x, ffma2(a0.y, q0.y,
                             ffma2(a1.x, q1.x, mul2(a1.y, q1.y)))));
    const float sb = f2_hsum(ffma2(b0.x, q0.x, ffma2(b0.y, q0.y,
                             ffma2(b1.x, q1.x, mul2(b1.y, q1.y)))));
    return fold2(sa, sb, 16, lane);
}

// ---------------------------------------------------------------------------
// Main kernel: per-warp cp.async pipelines; block couples only at Phase C.
// grid = 592 persistent blocks, block = 256. smem = 32KB ring + 8KB vbar.
// ---------------------------------------------------------------------------
__global__ __launch_bounds__(256)
void attn_cp_kernel(const char* __restrict__ key,
                    const char* __restrict__ value,
                    float* __restrict__ out) {
    const int tid  = threadIdx.x;
    const int w    = tid >> 5;
    const int lane = tid & 31;

    extern __shared__ float smem[];
    float* ring  = smem;                       // 8 warps * 1024 floats (4KB)
    float* vbarf = smem + 8192;                // 2048 floats
    __shared__ int s_tk[2];

    float* myring = ring + w * 1024;
    const uint32_t slot0 = (uint32_t)__cvta_generic_to_shared(myring);
    const uint32_t slot1 = slot0 + 2048;

    // bit-reversed t order so consecutive chunks form the fold tree
    const int ord[16] = {0,8,4,12,2,10,6,14,1,9,5,13,3,11,7,15};

    if (tid == 0) s_tk[0] = atomicAdd(&g_ticket, 1);
    __syncthreads();
    int p = 0;
    int tile = s_tk[0];

    const char* kitem = key;     // set properly below
    const char* vitem = value;
    if (tile < NTILES) {
        const int bi = tile >> 3, j = (tile & 7) * G + w;
        const size_t ib = (size_t)(bi * DL + j) * ITEM_BYTES;
        kitem = key + ib;  vitem = value + ib;
        issue_chunk(slot0, kitem, ord[0], lane);
        issue_chunk(slot1, kitem, ord[1], lane);
    }

    while (tile < NTILES) {
        const int bi = tile >> 3;
        const int j0 = (tile & 7) * G;

        const ulonglong2* qk2 = reinterpret_cast<const ulonglong2*>(g_Qk) + bi * 64;
        const ulonglong2 q0 = qk2[lane];
        const ulonglong2 q1 = qk2[32 + lane];

        // ---- Phase A: 16 K-chunks through the ring; eager tree fold ----
        // consK(c): wait, score, refill the freed slot with the next chunk.
        #define CONSK(c, nxt_tensor, nxt_t)                                   \
            cpwait1();                                                        \
            sc = score_chunk(myring + ((c) & 1) * 512, lane, q0, q1);         \
            issue_chunk(((c) & 1) ? slot1 : slot0, (nxt_tensor), (nxt_t), lane);

        float sc, h0, h1;
        {
            float s0, s1;
            CONSK(0,  kitem, ord[2]);  s0 = sc;
            CONSK(1,  kitem, ord[3]);  s1 = sc;
            float m08 = fold2(s0, s1, 8, lane);
            CONSK(2,  kitem, ord[4]);  s0 = sc;
            CONSK(3,  kitem, ord[5]);  s1 = sc;
            float qa = fold2(m08, fold2(s0, s1, 8, lane), 4, lane);
            CONSK(4,  kitem, ord[6]);  s0 = sc;
            CONSK(5,  kitem, ord[7]);  s1 = sc;
            float m2 = fold2(s0, s1, 8, lane);
            CONSK(6,  kitem, ord[8]);  s0 = sc;
            CONSK(7,  kitem, ord[9]);  s1 = sc;
            float qb = fold2(m2, fold2(s0, s1, 8, lane), 4, lane);
            h0 = fold2(qa, qb, 2, lane);
        }
        {
            float s0, s1;
            CONSK(8,  kitem, ord[10]); s0 = sc;
            CONSK(9,  kitem, ord[11]); s1 = sc;
            float m19 = fold2(s0, s1, 8, lane);
            CONSK(10, kitem, ord[12]); s0 = sc;
            CONSK(11, kitem, ord[13]); s1 = sc;
            float qc = fold2(m19, fold2(s0, s1, 8, lane), 4, lane);
            CONSK(12, kitem, ord[14]); s0 = sc;
            CONSK(13, kitem, ord[15]); s1 = sc;
            float m311 = fold2(s0, s1, 8, lane);
            CONSK(14, vitem, 0);       s0 = sc;   // start streaming V
            CONSK(15, vitem, 1);       s1 = sc;
            float qd = fold2(m311, fold2(s0, s1, 8, lane), 4, lane);
            h1 = fold2(qc, qd, 2, lane);
        }
        #undef CONSK
        const float myscore = fold2(h0, h1, 1, lane);   // lane l = score[t=l]

        // ---- warp-local softmax over T=32 ----
        float m = myscore;
#pragma unroll
        for (int off = 16; off; off >>= 1)
            m = fmaxf(m, __shfl_xor_sync(0xffffffffu, m, off));
        const float ex = __expf(myscore - m);
        float ssum = ex;
#pragma unroll
        for (int off = 16; off; off >>= 1)
            ssum += __shfl_xor_sync(0xffffffffu, ssum, off);
        const float a = ex / ssum;                      // attn[t = lane]

        // ---- Phase B: 16 V-chunks (rows vc, vc+16), packed accumulate ----
        unsigned long long b00 = 0ull, b01 = 0ull, b10 = 0ull, b11 = 0ull;
#pragma unroll
        for (int vc = 0; vc < 16; vc++) {
            if (vc < 15) cpwait1(); else cpwait0();
            const ulonglong2* s2 =
                reinterpret_cast<const ulonglong2*>(myring + (vc & 1) * 512);
            const float atA = __shfl_sync(0xffffffffu, a, vc);
            const float atB = __shfl_sync(0xffffffffu, a, vc + 16);
            const unsigned long long aA = f2_pack(atA, atA);
            const unsigned long long aB = f2_pack(atB, atB);
            const ulonglong2 vA0 = s2[lane],      vA1 = s2[32 + lane];
            const ulonglong2 vB0 = s2[64 + lane], vB1 = s2[96 + lane];
            b00 = ffma2(vA0.x, aA, b00); b01 = ffma2(vA0.y, aA, b01);
            b10 = ffma2(vA1.x, aA, b10); b11 = ffma2(vA1.y, aA, b11);
            b00 = ffma2(vB0.x, aB, b00); b01 = ffma2(vB0.y, aB, b01);
            b10 = ffma2(vB1.x, aB, b10); b11 = ffma2(vB1.y, aB, b11);
            if (vc < 14)
                issue_chunk((vc & 1) ? slot1 : slot0, vitem, vc + 2, lane);
        }

        ulonglong2* vb2 = reinterpret_cast<ulonglong2*>(vbarf);
        vb2[w * 64 + lane]      = make_ulonglong2(b00, b01);
        vb2[w * 64 + 32 + lane] = make_ulonglong2(b10, b11);

        if (tid == 0) s_tk[p ^ 1] = atomicAdd(&g_ticket, 1);
        __syncthreads();                                // vbar + next ticket
        const int ntile = s_tk[p ^ 1];

        // prefetch next item's first K chunks; they fly during Phase C
        if (ntile < NTILES) {
            const int nbi = ntile >> 3, nj = (ntile & 7) * G + w;
            const size_t nib = (size_t)(nbi * DL + nj) * ITEM_BYTES;
            kitem = key + nib;  vitem = value + nib;
            issue_chunk(slot0, kitem, ord[0], lane);
            issue_chunk(slot1, kitem, ord[1], lane);
        }

        // ---- Phase C: out[j0+jj, f] = bcomb[f] + vbar[jj] . Wcomb[:,f] ----
        {
            const int f = tid;
            unsigned long long acc2[G];
#pragma unroll
            for (int jj = 0; jj < G; jj++) acc2[jj] = 0ull;

            const ulonglong2* wp2 =
                reinterpret_cast<const ulonglong2*>(g_WcombP) + f;
#pragma unroll 4
            for (int d4 = 0; d4 < 64; d4++) {
                const ulonglong2 wp = __ldg(wp2 + d4 * DD);
#pragma unroll
                for (int jj = 0; jj < G; jj++) {
                    const ulonglong2 v = vb2[jj * 64 + d4];   // smem broadcast
                    acc2[jj] = ffma2(v.x, wp.x, acc2[jj]);
                    acc2[jj] = ffma2(v.y, wp.y, acc2[jj]);
                }
            }
            const float bc = __ldg(&g_bcomb[f]);
            const size_t obase = (size_t)(bi * DL + j0) * DD + f;
#pragma unroll
            for (int jj = 0; jj < G; jj++)
                __stcs(&out[obase + (size_t)jj * DD], f2_hsum(acc2[jj]) + bc);
        }
        __syncthreads();                                // vbar free for reuse
        tile = ntile;
        p ^= 1;
    }
}

// ---------------------------------------------------------------------------
// Launch. Input order: key, value, query, Wk, bk, Wv, bv, Wq, bq, Wf, bf
// ---------------------------------------------------------------------------
extern "C" void kernel_launch(void* const* d_in, const int* in_sizes, int n_in,
                              void* d_out, int out_size) {
    const float* key   = (const float*)d_in[0];
    const float* value = (const float*)d_in[1];
    const float* query = (const float*)d_in[2];
    const float* Wk    = (const float*)d_in[3];
    // bk (d_in[4]) cancels under softmax — unused.
    const float* Wv    = (const float*)d_in[5];
    const float* bv    = (const float*)d_in[6];
    const float* Wq    = (const float*)d_in[7];
    const float* bq    = (const float*)d_in[8];
    const float* Wf    = (const float*)d_in[9];
    const float* bf    = (const float*)d_in[10];
    float* out = (float*)d_out;

    prologue_kernel<<<193, dim3(32, 32)>>>(query, Wq, bq, Wk, Wv, bv, Wf, bf);

    const int smem_bytes = (8192 + 2048) * 4;   // 40KB: ring + vbar
    attn_cp_kernel<<<592, 256, smem_bytes>>>(
        reinterpret_cast<const char*>(key),
        reinterpret_cast<const char*>(value),
        out);
}

// round 12
// speedup vs baseline: 1.0017x; 1.0017x over previous
#include <cuda_runtime.h>
#include <cstdint>

#define DB 2     // batch
#define DL 64    // L
#define DT 32    // T
#define DD 256   // D
#define G  8     // j-columns per tile
#define NTILES (DB * DL * DL / G)   // 1024
#define ITEM_BYTES (DT * DD * 4)    // 32768 per tensor per item

// Scratch (device globals: no allocation allowed)
__device__ float g_Qk[DB * DL * DD];      // per (b,i): ((q@Wq^T+bq)/16)@Wk
__device__ float g_WcombP[64 * DD * 4];   // packed: [d4][f][4] = Wcomb[4*d4+r][f]
__device__ float g_bcomb[DD];             // bcomb[f] = sum_e Wf[f,e]*bv[e] + bf[f]
__device__ int   g_ticket;                // dynamic tile ticket

// ---------------------------------------------------------------------------
// f32x2 packed-FMA + cp.async helpers
// ---------------------------------------------------------------------------
__device__ __forceinline__ unsigned long long ffma2(unsigned long long a,
                                                    unsigned long long b,
                                                    unsigned long long c) {
    unsigned long long d;
    asm("fma.rn.f32x2 %0, %1, %2, %3;" : "=l"(d) : "l"(a), "l"(b), "l"(c));
    return d;
}
__device__ __forceinline__ unsigned long long mul2(unsigned long long a,
                                                   unsigned long long b) {
    unsigned long long d;
    asm("mul.rn.f32x2 %0, %1, %2;" : "=l"(d) : "l"(a), "l"(b));
    return d;
}
__device__ __forceinline__ unsigned long long f2_pack(float lo, float hi) {
    unsigned long long r;
    asm("mov.b64 %0, {%1, %2};" : "=l"(r) : "f"(lo), "f"(hi));
    return r;
}
__device__ __forceinline__ float f2_hsum(unsigned long long v) {
    float lo, hi;
    asm("mov.b64 {%0, %1}, %2;" : "=f"(lo), "=f"(hi) : "l"(v));
    return lo + hi;
}
__device__ __forceinline__ void cp16(uint32_t d, const void* s) {
    asm volatile("cp.async.cg.shared.global [%0], [%1], 16;"
                 :: "r"(d), "l"(s) : "memory");
}
__device__ __forceinline__ void cpcommit() {
    asm volatile("cp.async.commit_group;" ::: "memory");
}
__device__ __forceinline__ void cpwait1() {
    asm volatile("cp.async.wait_group 1;" ::: "memory");
}
__device__ __forceinline__ void cpwait0() {
    asm volatile("cp.async.wait_group 0;" ::: "memory");
}
__device__ __forceinline__ float fold2(float x, float y, int o, int lane) {
    const bool hi = (lane & o) != 0;
    const float send = hi ? x : y;
    const float recv = __shfl_xor_sync(0xffffffffu, send, o);
    return (hi ? y : x) + recv;
}

// ---------------------------------------------------------------------------
// Single prologue kernel, block = (32,32) = 1024 threads. (round-9, unchanged)
// ---------------------------------------------------------------------------
__global__ void prologue_kernel(const float* __restrict__ query,
                                const float* __restrict__ Wq,
                                const float* __restrict__ bq,
                                const float* __restrict__ Wk,
                                const float* __restrict__ Wv,
                                const float* __restrict__ bv,
                                const float* __restrict__ Wf,
                                const float* __restrict__ bf) {
    const int tx = threadIdx.x, ty = threadIdx.y;
    const int tid = ty * 32 + tx;
    const int blk = blockIdx.x;

    if (blk < 64) {
        __shared__ float Av[2][32][33];
        __shared__ float Bf[2][32][33];
        const int f0 = (blk & 7) * 32;
        const int d0 = (blk >> 3) * 32;

        Av[0][ty][tx] = Wv[(size_t)ty * DD + d0 + tx];
        Bf[0][ty][tx] = Wf[(size_t)(f0 + ty) * DD + tx];
        __syncthreads();

        float acc = 0.f;
#pragma unroll
        for (int s = 0; s < 8; s++) {
            const int cur = s & 1;
            if (s < 7) {
                const int e0 = (s + 1) * 32;
                Av[cur ^ 1][ty][tx] = Wv[(size_t)(e0 + ty) * DD + d0 + tx];
                Bf[cur ^ 1][ty][tx] = Wf[(size_t)(f0 + ty) * DD + e0 + tx];
            }
#pragma unroll
            for (int k = 0; k < 32; k++) acc += Av[cur][k][ty] * Bf[cur][tx][k];
            __syncthreads();
        }
        const int d = d0 + ty;
        const int f = f0 + tx;
        g_WcombP[(size_t)(d >> 2) * (DD * 4) + f * 4 + (d & 3)] = acc;

    } else if (blk < 192) {
        const int bi = blk - 64;
        __shared__ float q[DD];
        __shared__ float Qs[DD];
        __shared__ float part[4][DD];

        if (tid < DD) q[tid] = query[bi * DD + tid];
        __syncthreads();

#pragma unroll
        for (int i = 0; i < 8; i++) {
            const int e = ty * 8 + i;
            const float* wq = Wq + (size_t)e * DD;
            float p = 0.f;
#pragma unroll
            for (int c = 0; c < 8; c++) p += q[tx + 32 * c] * wq[tx + 32 * c];
#pragma unroll
            for (int off = 16; off; off >>= 1)
                p += __shfl_xor_sync(0xffffffffu, p, off);
            if (tx == 0) Qs[e] = (p + bq[e]) * 0.0625f;
        }
        __syncthreads();

        const int quarter = ty >> 3;
        const int d = tx + (ty & 7) * 32;
        const int e0 = quarter * 64;
        float acc = 0.f;
#pragma unroll 8
        for (int e = 0; e < 64; e++)
            acc += Qs[e0 + e] * Wk[(size_t)(e0 + e) * DD + d];
        part[quarter][d] = acc;
        __syncthreads();
        if (tid < DD)
            g_Qk[bi * DD + tid] = part[0][tid] + part[1][tid] + part[2][tid] + part[3][tid];

    } else {
        if (tid == 0) g_ticket = 0;
        __shared__ float bvs[DD];
        if (tid < DD) bvs[tid] = bv[tid];
        __syncthreads();
#pragma unroll
        for (int i = 0; i < 8; i++) {
            const int f = ty * 8 + i;
            const float* wf = Wf + (size_t)f * DD;
            float p = 0.f;
#pragma unroll
            for (int c = 0; c < 8; c++) p += bvs[tx + 32 * c] * wf[tx + 32 * c];
#pragma unroll
            for (int off = 16; off; off >>= 1)
                p += __shfl_xor_sync(0xffffffffu, p, off);
            if (tx == 0) g_bcomb[f] = p + bf[f];
        }
    }
}

// ---------------------------------------------------------------------------
// Chunk = rows (tA, tA+16) of one tensor, 2KB, staged into a per-warp slot.
// Each lane copies (and later reads) exactly its own 4x16B -> no syncwarp.
// ---------------------------------------------------------------------------
__device__ __forceinline__ void issue_chunk(uint32_t slot, const char* item,
                                            int tA, int lane) {
    const char* rA = item + tA * (DD * 4);
    const char* rB = item + (tA + 16) * (DD * 4);
    const uint32_t o = lane * 16;
    cp16(slot + o,        rA + o);
    cp16(slot + 512 + o,  rA + 512 + o);
    cp16(slot + 1024 + o, rB + o);
    cp16(slot + 1536 + o, rB + 512 + o);
    cpcommit();
}

__device__ __forceinline__ float score_chunk(const float* slot, int lane,
                                             const ulonglong2 q0,
                                             const ulonglong2 q1) {
    const ulonglong2* s2 = reinterpret_cast<const ulonglong2*>(slot);
    const ulonglong2 a0 = s2[lane],      a1 = s2[32 + lane];
    const ulonglong2 b0 = s2[64 + lane], b1 = s2[96 + lane];
    const float sa = f2_hsum(ffma2(a0.x, q0.x, ffma2(a0.y, q0.y,
                             ffma2(a1.x, q1.x, mul2(a1.y, q1.y)))));
    const float sb = f2_hsum(ffma2(b0.x, q0.x, ffma2(b0.y, q0.y,
                             ffma2(b1.x, q1.x, mul2(b1.y, q1.y)))));
    return fold2(sa, sb, 16, lane);
}

// ---------------------------------------------------------------------------
// Main kernel: per-warp cp.async pipelines; block couples only at Phase C.
// grid = 592 persistent blocks, block = 256. smem = 32KB ring + 8KB vbar.
// ---------------------------------------------------------------------------
__global__ __launch_bounds__(256)
void attn_cp_kernel(const char* __restrict__ key,
                    const char* __restrict__ value,
                    float* __restrict__ out) {
    const int tid  = threadIdx.x;
    const int w    = tid >> 5;
    const int lane = tid & 31;

    extern __shared__ float smem[];
    float* ring  = smem;                       // 8 warps * 1024 floats (4KB)
    float* vbarf = smem + 8192;                // 2048 floats
    __shared__ int s_tk[2];

    float* myring = ring + w * 1024;
    const uint32_t slot0 = (uint32_t)__cvta_generic_to_shared(myring);
    const uint32_t slot1 = slot0 + 2048;

    // bit-reversed t order so consecutive chunks form the fold tree
    const int ord[16] = {0,8,4,12,2,10,6,14,1,9,5,13,3,11,7,15};

    if (tid == 0) s_tk[0] = atomicAdd(&g_ticket, 1);
    __syncthreads();
    int p = 0;
    int tile = s_tk[0];

    const char* kitem = key;     // set properly below
    const char* vitem = value;
    if (tile < NTILES) {
        const int bi = tile >> 3, j = (tile & 7) * G + w;
        const size_t ib = (size_t)(bi * DL + j) * ITEM_BYTES;
        kitem = key + ib;  vitem = value + ib;
        issue_chunk(slot0, kitem, ord[0], lane);
        issue_chunk(slot1, kitem, ord[1], lane);
    }

    while (tile < NTILES) {
        const int bi = tile >> 3;
        const int j0 = (tile & 7) * G;

        const ulonglong2* qk2 = reinterpret_cast<const ulonglong2*>(g_Qk) + bi * 64;
        const ulonglong2 q0 = qk2[lane];
        const ulonglong2 q1 = qk2[32 + lane];

        // ---- Phase A: 16 K-chunks through the ring; eager tree fold ----
        // consK(c): wait, score, refill the freed slot with the next chunk.
        #define CONSK(c, nxt_tensor, nxt_t)                                   \
            cpwait1();                                                        \
            sc = score_chunk(myring + ((c) & 1) * 512, lane, q0, q1);         \
            issue_chunk(((c) & 1) ? slot1 : slot0, (nxt_tensor), (nxt_t), lane);

        float sc, h0, h1;
        {
            float s0, s1;
            CONSK(0,  kitem, ord[2]);  s0 = sc;
            CONSK(1,  kitem, ord[3]);  s1 = sc;
            float m08 = fold2(s0, s1, 8, lane);
            CONSK(2,  kitem, ord[4]);  s0 = sc;
            CONSK(3,  kitem, ord[5]);  s1 = sc;
            float qa = fold2(m08, fold2(s0, s1, 8, lane), 4, lane);
            CONSK(4,  kitem, ord[6]);  s0 = sc;
            CONSK(5,  kitem, ord[7]);  s1 = sc;
            float m2 = fold2(s0, s1, 8, lane);
            CONSK(6,  kitem, ord[8]);  s0 = sc;
            CONSK(7,  kitem, ord[9]);  s1 = sc;
            float qb = fold2(m2, fold2(s0, s1, 8, lane), 4, lane);
            h0 = fold2(qa, qb, 2, lane);
        }
        {
            float s0, s1;
            CONSK(8,  kitem, ord[10]); s0 = sc;
            CONSK(9,  kitem, ord[11]); s1 = sc;
            float m19 = fold2(s0, s1, 8, lane);
            CONSK(10, kitem, ord[12]); s0 = sc;
            CONSK(11, kitem, ord[13]); s1 = sc;
            float qc = fold2(m19, fold2(s0, s1, 8, lane), 4, lane);
            CONSK(12, kitem, ord[14]); s0 = sc;
            CONSK(13, kitem, ord[15]); s1 = sc;
            float m311 = fold2(s0, s1, 8, lane);
            CONSK(14, vitem, 0);       s0 = sc;   // start streaming V
            CONSK(15, vitem, 1);       s1 = sc;
            float qd = fold2(m311, fold2(s0, s1, 8, lane), 4, lane);
            h1 = fold2(qc, qd, 2, lane);
        }
        #undef CONSK
        const float myscore = fold2(h0, h1, 1, lane);   // lane l = score[t=l]

        // ---- warp-local softmax over T=32 ----
        float m = myscore;
#pragma unroll
        for (int off = 16; off; off >>= 1)
            m = fmaxf(m, __shfl_xor_sync(0xffffffffu, m, off));
        const float ex = __expf(myscore - m);
        float ssum = ex;
#pragma unroll
        for (int off = 16; off; off >>= 1)
            ssum += __shfl_xor_sync(0xffffffffu, ssum, off);
        const float a = ex / ssum;                      // attn[t = lane]

        // ---- Phase B: 16 V-chunks (rows vc, vc+16), packed accumulate ----
        unsigned long long b00 = 0ull, b01 = 0ull, b10 = 0ull, b11 = 0ull;
#pragma unroll
        for (int vc = 0; vc < 16; vc++) {
            if (vc < 15) cpwait1(); else cpwait0();
            const ulonglong2* s2 =
                reinterpret_cast<const ulonglong2*>(myring + (vc & 1) * 512);
            const float atA = __shfl_sync(0xffffffffu, a, vc);
            const float atB = __shfl_sync(0xffffffffu, a, vc + 16);
            const unsigned long long aA = f2_pack(atA, atA);
            const unsigned long long aB = f2_pack(atB, atB);
            const ulonglong2 vA0 = s2[lane],      vA1 = s2[32 + lane];
            const ulonglong2 vB0 = s2[64 + lane], vB1 = s2[96 + lane];
            b00 = ffma2(vA0.x, aA, b00); b01 = ffma2(vA0.y, aA, b01);
            b10 = ffma2(vA1.x, aA, b10); b11 = ffma2(vA1.y, aA, b11);
            b00 = ffma2(vB0.x, aB, b00); b01 = ffma2(vB0.y, aB, b01);
            b10 = ffma2(vB1.x, aB, b10); b11 = ffma2(vB1.y, aB, b11);
            if (vc < 14)
                issue_chunk((vc & 1) ? slot1 : slot0, vitem, vc + 2, lane);
        }

        ulonglong2* vb2 = reinterpret_cast<ulonglong2*>(vbarf);
        vb2[w * 64 + lane]      = make_ulonglong2(b00, b01);
        vb2[w * 64 + 32 + lane] = make_ulonglong2(b10, b11);

        if (tid == 0) s_tk[p ^ 1] = atomicAdd(&g_ticket, 1);
        __syncthreads();                                // vbar + next ticket
        const int ntile = s_tk[p ^ 1];

        // prefetch next item's first K chunks; they fly during Phase C
        if (ntile < NTILES) {
            const int nbi = ntile >> 3, nj = (ntile & 7) * G + w;
            const size_t nib = (size_t)(nbi * DL + nj) * ITEM_BYTES;
            kitem = key + nib;  vitem = value + nib;
            issue_chunk(slot0, kitem, ord[0], lane);
            issue_chunk(slot1, kitem, ord[1], lane);
        }

        // ---- Phase C: out[j0+jj, f] = bcomb[f] + vbar[jj] . Wcomb[:,f] ----
        {
            const int f = tid;
            unsigned long long acc2[G];
#pragma unroll
            for (int jj = 0; jj < G; jj++) acc2[jj] = 0ull;

            const ulonglong2* wp2 =
                reinterpret_cast<const ulonglong2*>(g_WcombP) + f;
#pragma unroll 4
            for (int d4 = 0; d4 < 64; d4++) {
                const ulonglong2 wp = __ldg(wp2 + d4 * DD);
#pragma unroll
                for (int jj = 0; jj < G; jj++) {
                    const ulonglong2 v = vb2[jj * 64 + d4];   // smem broadcast
                    acc2[jj] = ffma2(v.x, wp.x, acc2[jj]);
                    acc2[jj] = ffma2(v.y, wp.y, acc2[jj]);
                }
            }
            const float bc = __ldg(&g_bcomb[f]);
            const size_t obase = (size_t)(bi * DL + j0) * DD + f;
#pragma unroll
            for (int jj = 0; jj < G; jj++)
                __stcs(&out[obase + (size_t)jj * DD], f2_hsum(acc2[jj]) + bc);
        }
        __syncthreads();                                // vbar free for reuse
        tile = ntile;
        p ^= 1;
    }
}

// ---------------------------------------------------------------------------
// Launch. Input order: key, value, query, Wk, bk, Wv, bv, Wq, bq, Wf, bf
// ---------------------------------------------------------------------------
extern "C" void kernel_launch(void* const* d_in, const int* in_sizes, int n_in,
                              void* d_out, int out_size) {
    const float* key   = (const float*)d_in[0];
    const float* value = (const float*)d_in[1];
    const float* query = (const float*)d_in[2];
    const float* Wk    = (const float*)d_in[3];
    // bk (d_in[4]) cancels under softmax — unused.
    const float* Wv    = (const float*)d_in[5];
    const float* bv    = (const float*)d_in[6];
    const float* Wq    = (const float*)d_in[7];
    const float* bq    = (const float*)d_in[8];
    const float* Wf    = (const float*)d_in[9];
    const float* bf    = (const float*)d_in[10];
    float* out = (float*)d_out;

    prologue_kernel<<<193, dim3(32, 32)>>>(query, Wq, bq, Wk, Wv, bv, Wf, bf);

    const int smem_bytes = (8192 + 2048) * 4;   // 40KB: ring + vbar
    attn_cp_kernel<<<592, 256, smem_bytes>>>(
        reinterpret_cast<const char*>(key),
        reinterpret_cast<const char*>(value),
        out);
}

// round 13
// speedup vs baseline: 1.0178x; 1.0160x over previous
#include <cuda_runtime.h>
#include <cstdint>

#define DB 2     // batch
#define DL 64    // L
#define DT 32    // T
#define DD 256   // D
#define G  8     // j-columns per tile
#define NTILES (DB * DL * DL / G)   // 1024
#define ITEM_BYTES (DT * DD * 4)    // 32768 per tensor per item

// Scratch (device globals: no allocation allowed)
__device__ float g_Qk[DB * DL * DD];      // per (b,i): ((q@Wq^T+bq)/16)@Wk
__device__ float g_WcombP[64 * DD * 4];   // packed: [d4][f][4] = Wcomb[4*d4+r][f]
__device__ float g_bcomb[DD];             // bcomb[f] = sum_e Wf[f,e]*bv[e] + bf[f]
__device__ int   g_ticket;                // dynamic tile ticket

// ---------------------------------------------------------------------------
// f32x2 packed-FMA + cp.async helpers
// ---------------------------------------------------------------------------
__device__ __forceinline__ unsigned long long ffma2(unsigned long long a,
                                                    unsigned long long b,
                                                    unsigned long long c) {
    unsigned long long d;
    asm("fma.rn.f32x2 %0, %1, %2, %3;" : "=l"(d) : "l"(a), "l"(b), "l"(c));
    return d;
}
__device__ __forceinline__ unsigned long long mul2(unsigned long long a,
                                                   unsigned long long b) {
    unsigned long long d;
    asm("mul.rn.f32x2 %0, %1, %2;" : "=l"(d) : "l"(a), "l"(b));
    return d;
}
__device__ __forceinline__ unsigned long long f2_pack(float lo, float hi) {
    unsigned long long r;
    asm("mov.b64 %0, {%1, %2};" : "=l"(r) : "f"(lo), "f"(hi));
    return r;
}
__device__ __forceinline__ float f2_hsum(unsigned long long v) {
    float lo, hi;
    asm("mov.b64 {%0, %1}, %2;" : "=f"(lo), "=f"(hi) : "l"(v));
    return lo + hi;
}
__device__ __forceinline__ void cp16(uint32_t d, const void* s) {
    asm volatile("cp.async.cg.shared.global [%0], [%1], 16;"
                 :: "r"(d), "l"(s) : "memory");
}
__device__ __forceinline__ void cpcommit() {
    asm volatile("cp.async.commit_group;" ::: "memory");
}
__device__ __forceinline__ void cpwait1() {
    asm volatile("cp.async.wait_group 1;" ::: "memory");
}
__device__ __forceinline__ void cpwait0() {
    asm volatile("cp.async.wait_group 0;" ::: "memory");
}
__device__ __forceinline__ float fold2(float x, float y, int o, int lane) {
    const bool hi = (lane & o) != 0;
    const float send = hi ? x : y;
    const float recv = __shfl_xor_sync(0xffffffffu, send, o);
    return (hi ? y : x) + recv;
}

// ---------------------------------------------------------------------------
// Single prologue kernel, block = (32,32) = 1024 threads. (round-9, unchanged)
// ---------------------------------------------------------------------------
__global__ void prologue_kernel(const float* __restrict__ query,
                                const float* __restrict__ Wq,
                                const float* __restrict__ bq,
                                const float* __restrict__ Wk,
                                const float* __restrict__ Wv,
                                const float* __restrict__ bv,
                                const float* __restrict__ Wf,
                                const float* __restrict__ bf) {
    const int tx = threadIdx.x, ty = threadIdx.y;
    const int tid = ty * 32 + tx;
    const int blk = blockIdx.x;

    if (blk < 64) {
        __shared__ float Av[2][32][33];
        __shared__ float Bf[2][32][33];
        const int f0 = (blk & 7) * 32;
        const int d0 = (blk >> 3) * 32;

        Av[0][ty][tx] = Wv[(size_t)ty * DD + d0 + tx];
        Bf[0][ty][tx] = Wf[(size_t)(f0 + ty) * DD + tx];
        __syncthreads();

        float acc = 0.f;
#pragma unroll
        for (int s = 0; s < 8; s++) {
            const int cur = s & 1;
            if (s < 7) {
                const int e0 = (s + 1) * 32;
                Av[cur ^ 1][ty][tx] = Wv[(size_t)(e0 + ty) * DD + d0 + tx];
                Bf[cur ^ 1][ty][tx] = Wf[(size_t)(f0 + ty) * DD + e0 + tx];
            }
#pragma unroll
            for (int k = 0; k < 32; k++) acc += Av[cur][k][ty] * Bf[cur][tx][k];
            __syncthreads();
        }
        const int d = d0 + ty;
        const int f = f0 + tx;
        g_WcombP[(size_t)(d >> 2) * (DD * 4) + f * 4 + (d & 3)] = acc;

    } else if (blk < 192) {
        const int bi = blk - 64;
        __shared__ float q[DD];
        __shared__ float Qs[DD];
        __shared__ float part[4][DD];

        if (tid < DD) q[tid] = query[bi * DD + tid];
        __syncthreads();

#pragma unroll
        for (int i = 0; i < 8; i++) {
            const int e = ty * 8 + i;
            const float* wq = Wq + (size_t)e * DD;
            float p = 0.f;
#pragma unroll
            for (int c = 0; c < 8; c++) p += q[tx + 32 * c] * wq[tx + 32 * c];
#pragma unroll
            for (int off = 16; off; off >>= 1)
                p += __shfl_xor_sync(0xffffffffu, p, off);
            if (tx == 0) Qs[e] = (p + bq[e]) * 0.0625f;
        }
        __syncthreads();

        const int quarter = ty >> 3;
        const int d = tx + (ty & 7) * 32;
        const int e0 = quarter * 64;
        float acc = 0.f;
#pragma unroll 8
        for (int e = 0; e < 64; e++)
            acc += Qs[e0 + e] * Wk[(size_t)(e0 + e) * DD + d];
        part[quarter][d] = acc;
        __syncthreads();
        if (tid < DD)
            g_Qk[bi * DD + tid] = part[0][tid] + part[1][tid] + part[2][tid] + part[3][tid];

    } else {
        if (tid == 0) g_ticket = 0;
        __shared__ float bvs[DD];
        if (tid < DD) bvs[tid] = bv[tid];
        __syncthreads();
#pragma unroll
        for (int i = 0; i < 8; i++) {
            const int f = ty * 8 + i;
            const float* wf = Wf + (size_t)f * DD;
            float p = 0.f;
#pragma unroll
            for (int c = 0; c < 8; c++) p += bvs[tx + 32 * c] * wf[tx + 32 * c];
#pragma unroll
            for (int off = 16; off; off >>= 1)
                p += __shfl_xor_sync(0xffffffffu, p, off);
            if (tx == 0) g_bcomb[f] = p + bf[f];
        }
    }
}

// ---------------------------------------------------------------------------
// Chunk = rows (tA, tA+16) of one tensor, 2KB, staged into a per-warp slot.
// Each lane copies (and later reads) exactly its own 4x16B -> no syncwarp.
// ---------------------------------------------------------------------------
__device__ __forceinline__ void issue_chunk(uint32_t slot, const char* item,
                                            int tA, int lane) {
    const char* rA = item + tA * (DD * 4);
    const char* rB = item + (tA + 16) * (DD * 4);
    const uint32_t o = lane * 16;
    cp16(slot + o,        rA + o);
    cp16(slot + 512 + o,  rA + 512 + o);
    cp16(slot + 1024 + o, rB + o);
    cp16(slot + 1536 + o, rB + 512 + o);
    cpcommit();
}

__device__ __forceinline__ float score_chunk(const float* slot, int lane,
                                             const ulonglong2 q0,
                                             const ulonglong2 q1) {
    const ulonglong2* s2 = reinterpret_cast<const ulonglong2*>(slot);
    const ulonglong2 a0 = s2[lane],      a1 = s2[32 + lane];
    const ulonglong2 b0 = s2[64 + lane], b1 = s2[96 + lane];
    const float sa = f2_hsum(ffma2(a0.x, q0.x, ffma2(a0.y, q0.y,
                             ffma2(a1.x, q1.x, mul2(a1.y, q1.y)))));
    const float sb = f2_hsum(ffma2(b0.x, q0.x, ffma2(b0.y, q0.y,
                             ffma2(b1.x, q1.x, mul2(b1.y, q1.y)))));
    return fold2(sa, sb, 16, lane);
}

// ---------------------------------------------------------------------------
// Main kernel: per-warp cp.async pipelines; block couples only at Phase C.
// grid = 592 persistent blocks, block = 256. smem = 32KB ring + 8KB vbar.
// ---------------------------------------------------------------------------
__global__ __launch_bounds__(256)
void attn_cp_kernel(const char* __restrict__ key,
                    const char* __restrict__ value,
                    float* __restrict__ out) {
    const int tid  = threadIdx.x;
    const int w    = tid >> 5;
    const int lane = tid & 31;

    extern __shared__ float smem[];
    float* ring  = smem;                       // 8 warps * 1024 floats (4KB)
    float* vbarf = smem + 8192;                // 2048 floats
    __shared__ int s_tk[2];

    float* myring = ring + w * 1024;
    const uint32_t slot0 = (uint32_t)__cvta_generic_to_shared(myring);
    const uint32_t slot1 = slot0 + 2048;

    // bit-reversed t order so consecutive chunks form the fold tree
    const int ord[16] = {0,8,4,12,2,10,6,14,1,9,5,13,3,11,7,15};

    if (tid == 0) s_tk[0] = atomicAdd(&g_ticket, 1);
    __syncthreads();
    int p = 0;
    int tile = s_tk[0];

    const char* kitem = key;     // set properly below
    const char* vitem = value;
    if (tile < NTILES) {
        const int bi = tile >> 3, j = (tile & 7) * G + w;
        const size_t ib = (size_t)(bi * DL + j) * ITEM_BYTES;
        kitem = key + ib;  vitem = value + ib;
        issue_chunk(slot0, kitem, ord[0], lane);
        issue_chunk(slot1, kitem, ord[1], lane);
    }

    while (tile < NTILES) {
        const int bi = tile >> 3;
        const int j0 = (tile & 7) * G;

        const ulonglong2* qk2 = reinterpret_cast<const ulonglong2*>(g_Qk) + bi * 64;
        const ulonglong2 q0 = qk2[lane];
        const ulonglong2 q1 = qk2[32 + lane];

        // ---- Phase A: 16 K-chunks through the ring; eager tree fold ----
        // consK(c): wait, score, refill the freed slot with the next chunk.
        #define CONSK(c, nxt_tensor, nxt_t)                                   \
            cpwait1();                                                        \
            sc = score_chunk(myring + ((c) & 1) * 512, lane, q0, q1);         \
            issue_chunk(((c) & 1) ? slot1 : slot0, (nxt_tensor), (nxt_t), lane);

        float sc, h0, h1;
        {
            float s0, s1;
            CONSK(0,  kitem, ord[2]);  s0 = sc;
            CONSK(1,  kitem, ord[3]);  s1 = sc;
            float m08 = fold2(s0, s1, 8, lane);
            CONSK(2,  kitem, ord[4]);  s0 = sc;
            CONSK(3,  kitem, ord[5]);  s1 = sc;
            float qa = fold2(m08, fold2(s0, s1, 8, lane), 4, lane);
            CONSK(4,  kitem, ord[6]);  s0 = sc;
            CONSK(5,  kitem, ord[7]);  s1 = sc;
            float m2 = fold2(s0, s1, 8, lane);
            CONSK(6,  kitem, ord[8]);  s0 = sc;
            CONSK(7,  kitem, ord[9]);  s1 = sc;
            float qb = fold2(m2, fold2(s0, s1, 8, lane), 4, lane);
            h0 = fold2(qa, qb, 2, lane);
        }
        {
            float s0, s1;
            CONSK(8,  kitem, ord[10]); s0 = sc;
            CONSK(9,  kitem, ord[11]); s1 = sc;
            float m19 = fold2(s0, s1, 8, lane);
            CONSK(10, kitem, ord[12]); s0 = sc;
            CONSK(11, kitem, ord[13]); s1 = sc;
            float qc = fold2(m19, fold2(s0, s1, 8, lane), 4, lane);
            CONSK(12, kitem, ord[14]); s0 = sc;
            CONSK(13, kitem, ord[15]); s1 = sc;
            float m311 = fold2(s0, s1, 8, lane);
            CONSK(14, vitem, 0);       s0 = sc;   // start streaming V
            CONSK(15, vitem, 1);       s1 = sc;
            float qd = fold2(m311, fold2(s0, s1, 8, lane), 4, lane);
            h1 = fold2(qc, qd, 2, lane);
        }
        #undef CONSK
        const float myscore = fold2(h0, h1, 1, lane);   // lane l = score[t=l]

        // ---- warp-local softmax over T=32 ----
        float m = myscore;
#pragma unroll
        for (int off = 16; off; off >>= 1)
            m = fmaxf(m, __shfl_xor_sync(0xffffffffu, m, off));
        const float ex = __expf(myscore - m);
        float ssum = ex;
#pragma unroll
        for (int off = 16; off; off >>= 1)
            ssum += __shfl_xor_sync(0xffffffffu, ssum, off);
        const float a = ex / ssum;                      // attn[t = lane]

        // ---- Phase B: 16 V-chunks (rows vc, vc+16), packed accumulate ----
        unsigned long long b00 = 0ull, b01 = 0ull, b10 = 0ull, b11 = 0ull;
#pragma unroll
        for (int vc = 0; vc < 16; vc++) {
            if (vc < 15) cpwait1(); else cpwait0();
            const ulonglong2* s2 =
                reinterpret_cast<const ulonglong2*>(myring + (vc & 1) * 512);
            const float atA = __shfl_sync(0xffffffffu, a, vc);
            const float atB = __shfl_sync(0xffffffffu, a, vc + 16);
            const unsigned long long aA = f2_pack(atA, atA);
            const unsigned long long aB = f2_pack(atB, atB);
            const ulonglong2 vA0 = s2[lane],      vA1 = s2[32 + lane];
            const ulonglong2 vB0 = s2[64 + lane], vB1 = s2[96 + lane];
            b00 = ffma2(vA0.x, aA, b00); b01 = ffma2(vA0.y, aA, b01);
            b10 = ffma2(vA1.x, aA, b10); b11 = ffma2(vA1.y, aA, b11);
            b00 = ffma2(vB0.x, aB, b00); b01 = ffma2(vB0.y, aB, b01);
            b10 = ffma2(vB1.x, aB, b10); b11 = ffma2(vB1.y, aB, b11);
            if (vc < 14)
                issue_chunk((vc & 1) ? slot1 : slot0, vitem, vc + 2, lane);
        }

        ulonglong2* vb2 = reinterpret_cast<ulonglong2*>(vbarf);
        vb2[w * 64 + lane]      = make_ulonglong2(b00, b01);
        vb2[w * 64 + 32 + lane] = make_ulonglong2(b10, b11);

        if (tid == 0) s_tk[p ^ 1] = atomicAdd(&g_ticket, 1);
        __syncthreads();                                // vbar + next ticket
        const int ntile = s_tk[p ^ 1];

        // prefetch next item's first K chunks; they fly during Phase C
        if (ntile < NTILES) {
            const int nbi = ntile >> 3, nj = (ntile & 7) * G + w;
            const size_t nib = (size_t)(nbi * DL + nj) * ITEM_BYTES;
            kitem = key + nib;  vitem = value + nib;
            issue_chunk(slot0, kitem, ord[0], lane);
            issue_chunk(slot1, kitem, ord[1], lane);
        }

        // ---- Phase C: out[j0+jj, f] = bcomb[f] + vbar[jj] . Wcomb[:,f] ----
        {
            const int f = tid;
            unsigned long long acc2[G];
#pragma unroll
            for (int jj = 0; jj < G; jj++) acc2[jj] = 0ull;

            const ulonglong2* wp2 =
                reinterpret_cast<const ulonglong2*>(g_WcombP) + f;
#pragma unroll 4
            for (int d4 = 0; d4 < 64; d4++) {
                const ulonglong2 wp = __ldg(wp2 + d4 * DD);
#pragma unroll
                for (int jj = 0; jj < G; jj++) {
                    const ulonglong2 v = vb2[jj * 64 + d4];   // smem broadcast
                    acc2[jj] = ffma2(v.x, wp.x, acc2[jj]);
                    acc2[jj] = ffma2(v.y, wp.y, acc2[jj]);
                }
            }
            const float bc = __ldg(&g_bcomb[f]);
            const size_t obase = (size_t)(bi * DL + j0) * DD + f;
#pragma unroll
            for (int jj = 0; jj < G; jj++)
                __stcs(&out[obase + (size_t)jj * DD], f2_hsum(acc2[jj]) + bc);
        }
        __syncthreads();                                // vbar free for reuse
        tile = ntile;
        p ^= 1;
    }
}

// ---------------------------------------------------------------------------
// Launch. Input order: key, value, query, Wk, bk, Wv, bv, Wq, bq, Wf, bf
// ---------------------------------------------------------------------------
extern "C" void kernel_launch(void* const* d_in, const int* in_sizes, int n_in,
                              void* d_out, int out_size) {
    const float* key   = (const float*)d_in[0];
    const float* value = (const float*)d_in[1];
    const float* query = (const float*)d_in[2];
    const float* Wk    = (const float*)d_in[3];
    // bk (d_in[4]) cancels under softmax — unused.
    const float* Wv    = (const float*)d_in[5];
    const float* bv    = (const float*)d_in[6];
    const float* Wq    = (const float*)d_in[7];
    const float* bq    = (const float*)d_in[8];
    const float* Wf    = (const float*)d_in[9];
    const float* bf    = (const float*)d_in[10];
    float* out = (float*)d_out;

    prologue_kernel<<<193, dim3(32, 32)>>>(query, Wq, bq, Wk, Wv, bv, Wf, bf);

    const int smem_bytes = (8192 + 2048) * 4;   // 40KB: ring + vbar
    attn_cp_kernel<<<592, 256, smem_bytes>>>(
        reinterpret_cast<const char*>(key),
        reinterpret_cast<const char*>(value),
        out);
}